// round 1
// baseline (speedup 1.0000x reference)
#include <cuda_runtime.h>

#define EMB 128
#define MAX_ATOMS 20000
#define AS 132   // padded smem row stride (floats)

// Scratch: segment-sum accumulator (10.24 MB). Static device global: no allocs.
__device__ float g_node[MAX_ATOMS * EMB];
__device__ int g_is64;

// ---------------------------------------------------------------------------
// Detect whether nbr_list is int64 or int32.
// If int64: every odd 32-bit word in the first 1024 pairs is a zero hi-word
// (all indices < 20000). If int32: odd words are dst indices, ~all nonzero.
// ---------------------------------------------------------------------------
__global__ void detect_dtype_kernel(const int* __restrict__ nbr, int n_words) {
    __shared__ int any;
    if (threadIdx.x == 0) any = 0;
    __syncthreads();
    int found = 0;
    for (int i = threadIdx.x; i < 2048; i += blockDim.x) {
        int idx = 2 * i + 1;
        if (idx < n_words && nbr[idx] != 0) found = 1;
    }
    if (found) atomicOr(&any, 1);
    __syncthreads();
    if (threadIdx.x == 0) g_is64 = (any == 0) ? 1 : 0;
}

__global__ void zero_kernel(int n) {
    int i = blockIdx.x * blockDim.x + threadIdx.x;
    if (i < n) g_node[i] = 0.0f;
}

// ---------------------------------------------------------------------------
// Edge pass: one warp per edge.
// prod[c] = (sum_r e_rbf[e][r] * W_edge[r][c]) * m_ji[e][c]; red into g_node[dst].
// Vector float4 atomicAdd (sm_90+) quarters the red-op count.
// ---------------------------------------------------------------------------
__global__ void __launch_bounds__(256) edge_kernel(
    const float* __restrict__ m_ji,
    const float* __restrict__ e_rbf,
    const int*   __restrict__ nbr,
    const float* __restrict__ W_edge,
    int E)
{
    __shared__ float sWe[6 * 128];
    int tid = threadIdx.x;
    for (int i = tid; i < 6 * 128; i += blockDim.x) sWe[i] = W_edge[i];
    __syncthreads();

    int warp = (int)((blockIdx.x * (long long)blockDim.x + tid) >> 5);
    int lane = tid & 31;
    if (warp >= E) return;

    long long e = warp;
    int is64 = g_is64;

    float rbf_l = (lane < 6) ? __ldg(&e_rbf[e * 6 + lane]) : 0.0f;
    int dst = is64 ? __ldg(&nbr[e * 4 + 2]) : __ldg(&nbr[e * 2 + 1]);

    const float4* mrow = reinterpret_cast<const float4*>(m_ji + e * EMB);
    float4 m4 = __ldg(&mrow[lane]);

    const float4* we4 = reinterpret_cast<const float4*>(sWe);
    float4 w = make_float4(0.f, 0.f, 0.f, 0.f);
#pragma unroll
    for (int r = 0; r < 6; r++) {
        float c = __shfl_sync(0xffffffffu, rbf_l, r);
        float4 v = we4[r * 32 + lane];
        w.x = fmaf(c, v.x, w.x);
        w.y = fmaf(c, v.y, w.y);
        w.z = fmaf(c, v.z, w.z);
        w.w = fmaf(c, v.w, w.w);
    }
    float4 out = make_float4(w.x * m4.x, w.y * m4.y, w.z * m4.z, w.w * m4.w);

    float4* dstp = reinterpret_cast<float4*>(&g_node[(long long)dst * EMB + lane * 4]);
    atomicAdd(dstp, out);
}

// ---------------------------------------------------------------------------
// Fused 4-layer MLP. 128 rows per CTA, 256 threads, 8x8 register tiles.
// act and W both live in SMEM (2 * 128*AS floats + 128-float bias).
// ---------------------------------------------------------------------------
__global__ void __launch_bounds__(256, 1) mlp_kernel(
    const float* __restrict__ W1, const float* __restrict__ b1,
    const float* __restrict__ W2, const float* __restrict__ b2,
    const float* __restrict__ W3, const float* __restrict__ b3,
    const float* __restrict__ W4,
    float* __restrict__ out, int natoms)
{
    extern __shared__ float sm[];
    float* act = sm;                   // 128 * AS
    float* wsm = sm + 128 * AS;        // 128 * AS
    float* bia = sm + 2 * 128 * AS;    // 128

    int tid = threadIdx.x;
    int row0 = blockIdx.x * 128;

    // Load initial activations from the segment-sum buffer.
    for (int i = tid; i < 128 * 128; i += 256) {
        int r = i >> 7, c = i & 127;
        int gr = row0 + r;
        act[r * AS + c] = (gr < natoms) ? g_node[gr * EMB + c] : 0.0f;
    }

    const float* Ws[4] = {W1, W2, W3, W4};
    const float* Bs[3] = {b1, b2, b3};

    int ty = tid >> 4;   // 0..15: row group of 8
    int tx = tid & 15;   // 0..15: col group of 8

    for (int layer = 0; layer < 4; layer++) {
        __syncthreads();   // prior act writeback + prior W reads complete
        const float* W = Ws[layer];
        for (int i = tid; i < 128 * 128; i += 256) {
            int r = i >> 7, c = i & 127;
            wsm[r * AS + c] = W[i];
        }
        if (layer < 3 && tid < 128) bia[tid] = Bs[layer][tid];
        __syncthreads();

        float acc[8][8];
#pragma unroll
        for (int i = 0; i < 8; i++)
#pragma unroll
            for (int j = 0; j < 8; j++) acc[i][j] = 0.0f;

#pragma unroll 4
        for (int k = 0; k < 128; k++) {
            float a[8], b[8];
#pragma unroll
            for (int i = 0; i < 8; i++) a[i] = act[(ty * 8 + i) * AS + k];
            float4 bv0 = *reinterpret_cast<const float4*>(&wsm[k * AS + tx * 8]);
            float4 bv1 = *reinterpret_cast<const float4*>(&wsm[k * AS + tx * 8 + 4]);
            b[0] = bv0.x; b[1] = bv0.y; b[2] = bv0.z; b[3] = bv0.w;
            b[4] = bv1.x; b[5] = bv1.y; b[6] = bv1.z; b[7] = bv1.w;
#pragma unroll
            for (int i = 0; i < 8; i++)
#pragma unroll
                for (int j = 0; j < 8; j++)
                    acc[i][j] = fmaf(a[i], b[j], acc[i][j]);
        }
        __syncthreads();  // all act/wsm reads done before writeback

        if (layer < 3) {
#pragma unroll
            for (int i = 0; i < 8; i++)
#pragma unroll
                for (int j = 0; j < 8; j++) {
                    float x = acc[i][j] + bia[tx * 8 + j];
                    x = x / (1.0f + __expf(-x));   // swish
                    act[(ty * 8 + i) * AS + tx * 8 + j] = x;
                }
        } else {
#pragma unroll
            for (int i = 0; i < 8; i++) {
                int gr = row0 + ty * 8 + i;
                if (gr < natoms) {
#pragma unroll
                    for (int j = 0; j < 8; j++)
                        out[(long long)gr * EMB + tx * 8 + j] = acc[i][j];
                }
            }
        }
    }
}

// ---------------------------------------------------------------------------
extern "C" void kernel_launch(void* const* d_in, const int* in_sizes, int n_in,
                              void* d_out, int out_size)
{
    const float* m_ji  = (const float*)d_in[0];
    const float* e_rbf = (const float*)d_in[1];
    const int*   nbr   = (const int*)d_in[2];

    // If num_atoms scalar is present as a tiny buffer at index 3, weights start at 4.
    int base = (n_in >= 12 && in_sizes[3] < 16) ? 4 : 3;
    const float* W_edge = (const float*)d_in[base + 0];
    const float* W1 = (const float*)d_in[base + 1];
    const float* b1 = (const float*)d_in[base + 2];
    const float* W2 = (const float*)d_in[base + 3];
    const float* b2 = (const float*)d_in[base + 4];
    const float* W3 = (const float*)d_in[base + 5];
    const float* b3 = (const float*)d_in[base + 6];
    const float* W4 = (const float*)d_in[base + 7];

    int E = in_sizes[1] / 6;            // e_rbf is (E, 6)
    int natoms = out_size / EMB;        // output is (natoms, 128)
    if (natoms > MAX_ATOMS) natoms = MAX_ATOMS;
    float* out = (float*)d_out;

    // 1) dtype detection for nbr_list (int32 vs int64)
    detect_dtype_kernel<<<1, 256>>>(nbr, 2 * E);

    // 2) zero the segment-sum accumulator
    int nz = natoms * EMB;
    zero_kernel<<<(nz + 255) / 256, 256>>>(nz);

    // 3) edge pass: one warp per edge
    int blocks = (E + 7) / 8;   // 8 warps (edges) per 256-thread block
    edge_kernel<<<blocks, 256>>>(m_ji, e_rbf, nbr, W_edge, E);

    // 4) fused MLP
    size_t smem = (size_t)(2 * 128 * AS + 128) * sizeof(float);
    cudaFuncSetAttribute(mlp_kernel, cudaFuncAttributeMaxDynamicSharedMemorySize, (int)smem);
    int mlp_blocks = (natoms + 127) / 128;
    mlp_kernel<<<mlp_blocks, 256, smem>>>(W1, b1, W2, b2, W3, b3, W4, out, natoms);
}

// round 2
// speedup vs baseline: 1.2266x; 1.2266x over previous
#include <cuda_runtime.h>

#define EMB 128
#define MAX_ATOMS 20000
#define AS 132   // padded smem row stride (floats)

// Scratch: segment-sum accumulator (10.24 MB). Static device global: no allocs.
__device__ float g_node[MAX_ATOMS * EMB];
__device__ int g_is64;

// ---------------------------------------------------------------------------
// Detect whether nbr_list is int64 or int32.
// ---------------------------------------------------------------------------
__global__ void detect_dtype_kernel(const int* __restrict__ nbr, int n_words) {
    __shared__ int any;
    if (threadIdx.x == 0) any = 0;
    __syncthreads();
    int found = 0;
    for (int i = threadIdx.x; i < 2048; i += blockDim.x) {
        int idx = 2 * i + 1;
        if (idx < n_words && nbr[idx] != 0) found = 1;
    }
    if (found) atomicOr(&any, 1);
    __syncthreads();
    if (threadIdx.x == 0) g_is64 = (any == 0) ? 1 : 0;
}

__global__ void zero_kernel(int n) {
    int i = blockIdx.x * blockDim.x + threadIdx.x;
    if (i < n) g_node[i] = 0.0f;
}

// ---------------------------------------------------------------------------
// Edge pass: one warp per edge, float4 atomicAdd scatter into g_node.
// ---------------------------------------------------------------------------
__global__ void __launch_bounds__(256) edge_kernel(
    const float* __restrict__ m_ji,
    const float* __restrict__ e_rbf,
    const int*   __restrict__ nbr,
    const float* __restrict__ W_edge,
    int E)
{
    __shared__ float sWe[6 * 128];
    int tid = threadIdx.x;
    for (int i = tid; i < 6 * 128; i += blockDim.x) sWe[i] = W_edge[i];
    __syncthreads();

    int warp = (int)((blockIdx.x * (long long)blockDim.x + tid) >> 5);
    int lane = tid & 31;
    if (warp >= E) return;

    long long e = warp;
    int is64 = g_is64;

    float rbf_l = (lane < 6) ? __ldg(&e_rbf[e * 6 + lane]) : 0.0f;
    int dst = is64 ? __ldg(&nbr[e * 4 + 2]) : __ldg(&nbr[e * 2 + 1]);

    const float4* mrow = reinterpret_cast<const float4*>(m_ji + e * EMB);
    float4 m4 = __ldg(&mrow[lane]);

    const float4* we4 = reinterpret_cast<const float4*>(sWe);
    float4 w = make_float4(0.f, 0.f, 0.f, 0.f);
#pragma unroll
    for (int r = 0; r < 6; r++) {
        float c = __shfl_sync(0xffffffffu, rbf_l, r);
        float4 v = we4[r * 32 + lane];
        w.x = fmaf(c, v.x, w.x);
        w.y = fmaf(c, v.y, w.y);
        w.z = fmaf(c, v.z, w.z);
        w.w = fmaf(c, v.w, w.w);
    }
    float4 out = make_float4(w.x * m4.x, w.y * m4.y, w.z * m4.z, w.w * m4.w);

    float4* dstp = reinterpret_cast<float4*>(&g_node[(long long)dst * EMB + lane * 4]);
    atomicAdd(dstp, out);
}

// ---------------------------------------------------------------------------
// Fused 4-layer MLP v2. 128 rows per CTA, 512 threads, 4x8 register tiles.
// k batched by 4 with float4 smem loads so LDS latency is pipelined.
// ---------------------------------------------------------------------------
__global__ void __launch_bounds__(512, 1) mlp_kernel(
    const float* __restrict__ W1, const float* __restrict__ b1,
    const float* __restrict__ W2, const float* __restrict__ b2,
    const float* __restrict__ W3, const float* __restrict__ b3,
    const float* __restrict__ W4,
    float* __restrict__ out, int natoms)
{
    extern __shared__ float sm[];
    float* act = sm;                   // 128 * AS
    float* wsm = sm + 128 * AS;        // 128 * AS
    float* bia = sm + 2 * 128 * AS;    // 128

    int tid = threadIdx.x;
    int row0 = blockIdx.x * 128;

    // Load initial activations (float4 granularity).
    for (int i = tid; i < 128 * 32; i += 512) {
        int r = i >> 5, c4 = i & 31;
        int gr = row0 + r;
        float4 v = make_float4(0.f, 0.f, 0.f, 0.f);
        if (gr < natoms)
            v = *reinterpret_cast<const float4*>(&g_node[(long long)gr * EMB + c4 * 4]);
        *reinterpret_cast<float4*>(&act[r * AS + c4 * 4]) = v;
    }

    const float* Ws[4] = {W1, W2, W3, W4};
    const float* Bs[3] = {b1, b2, b3};

    int ty = tid >> 4;   // 0..31: row group of 4
    int tx = tid & 15;   // 0..15: col group of 8

    for (int layer = 0; layer < 4; layer++) {
        __syncthreads();   // prior act writeback + prior W reads complete
        const float* W = Ws[layer];
        for (int i = tid; i < 128 * 32; i += 512) {
            int r = i >> 5, c4 = i & 31;
            *reinterpret_cast<float4*>(&wsm[r * AS + c4 * 4]) =
                *reinterpret_cast<const float4*>(&W[r * 128 + c4 * 4]);
        }
        if (layer < 3 && tid < 128) bia[tid] = Bs[layer][tid];
        __syncthreads();

        float acc[4][8];
#pragma unroll
        for (int i = 0; i < 4; i++)
#pragma unroll
            for (int j = 0; j < 8; j++) acc[i][j] = 0.0f;

#pragma unroll 2
        for (int k0 = 0; k0 < 128; k0 += 4) {
            // 4 rows x 4 k-values of activations, vectorized
            float4 a4[4];
#pragma unroll
            for (int i = 0; i < 4; i++)
                a4[i] = *reinterpret_cast<const float4*>(&act[(ty * 4 + i) * AS + k0]);

            // 4 k-slices of 8 weight columns each
            float4 b0[4], b1v[4];
#pragma unroll
            for (int kk = 0; kk < 4; kk++) {
                b0[kk]  = *reinterpret_cast<const float4*>(&wsm[(k0 + kk) * AS + tx * 8]);
                b1v[kk] = *reinterpret_cast<const float4*>(&wsm[(k0 + kk) * AS + tx * 8 + 4]);
            }

#pragma unroll
            for (int kk = 0; kk < 4; kk++) {
                float b[8];
                b[0] = b0[kk].x; b[1] = b0[kk].y; b[2] = b0[kk].z; b[3] = b0[kk].w;
                b[4] = b1v[kk].x; b[5] = b1v[kk].y; b[6] = b1v[kk].z; b[7] = b1v[kk].w;
#pragma unroll
                for (int i = 0; i < 4; i++) {
                    float av = reinterpret_cast<const float*>(&a4[i])[kk];
#pragma unroll
                    for (int j = 0; j < 8; j++)
                        acc[i][j] = fmaf(av, b[j], acc[i][j]);
                }
            }
        }
        __syncthreads();  // all act/wsm reads done before writeback

        if (layer < 3) {
#pragma unroll
            for (int i = 0; i < 4; i++) {
                float4 o0, o1;
                float* accp = acc[i];
                float r0 = accp[0] + bia[tx * 8 + 0];
                float r1 = accp[1] + bia[tx * 8 + 1];
                float r2 = accp[2] + bia[tx * 8 + 2];
                float r3 = accp[3] + bia[tx * 8 + 3];
                float r4 = accp[4] + bia[tx * 8 + 4];
                float r5 = accp[5] + bia[tx * 8 + 5];
                float r6 = accp[6] + bia[tx * 8 + 6];
                float r7 = accp[7] + bia[tx * 8 + 7];
                o0.x = r0 / (1.0f + __expf(-r0));
                o0.y = r1 / (1.0f + __expf(-r1));
                o0.z = r2 / (1.0f + __expf(-r2));
                o0.w = r3 / (1.0f + __expf(-r3));
                o1.x = r4 / (1.0f + __expf(-r4));
                o1.y = r5 / (1.0f + __expf(-r5));
                o1.z = r6 / (1.0f + __expf(-r6));
                o1.w = r7 / (1.0f + __expf(-r7));
                *reinterpret_cast<float4*>(&act[(ty * 4 + i) * AS + tx * 8]) = o0;
                *reinterpret_cast<float4*>(&act[(ty * 4 + i) * AS + tx * 8 + 4]) = o1;
            }
        } else {
#pragma unroll
            for (int i = 0; i < 4; i++) {
                int gr = row0 + ty * 4 + i;
                if (gr < natoms) {
                    float4 o0 = make_float4(acc[i][0], acc[i][1], acc[i][2], acc[i][3]);
                    float4 o1 = make_float4(acc[i][4], acc[i][5], acc[i][6], acc[i][7]);
                    *reinterpret_cast<float4*>(&out[(long long)gr * EMB + tx * 8]) = o0;
                    *reinterpret_cast<float4*>(&out[(long long)gr * EMB + tx * 8 + 4]) = o1;
                }
            }
        }
    }
}

// ---------------------------------------------------------------------------
extern "C" void kernel_launch(void* const* d_in, const int* in_sizes, int n_in,
                              void* d_out, int out_size)
{
    const float* m_ji  = (const float*)d_in[0];
    const float* e_rbf = (const float*)d_in[1];
    const int*   nbr   = (const int*)d_in[2];

    int base = (n_in >= 12 && in_sizes[3] < 16) ? 4 : 3;
    const float* W_edge = (const float*)d_in[base + 0];
    const float* W1 = (const float*)d_in[base + 1];
    const float* b1 = (const float*)d_in[base + 2];
    const float* W2 = (const float*)d_in[base + 3];
    const float* b2 = (const float*)d_in[base + 4];
    const float* W3 = (const float*)d_in[base + 5];
    const float* b3 = (const float*)d_in[base + 6];
    const float* W4 = (const float*)d_in[base + 7];

    int E = in_sizes[1] / 6;            // e_rbf is (E, 6)
    int natoms = out_size / EMB;        // output is (natoms, 128)
    if (natoms > MAX_ATOMS) natoms = MAX_ATOMS;
    float* out = (float*)d_out;

    // 1) dtype detection for nbr_list (int32 vs int64)
    detect_dtype_kernel<<<1, 256>>>(nbr, 2 * E);

    // 2) zero the segment-sum accumulator
    int nz = natoms * EMB;
    zero_kernel<<<(nz + 255) / 256, 256>>>(nz);

    // 3) edge pass: one warp per edge
    int blocks = (E + 7) / 8;   // 8 warps (edges) per 256-thread block
    edge_kernel<<<blocks, 256>>>(m_ji, e_rbf, nbr, W_edge, E);

    // 4) fused MLP
    size_t smem = (size_t)(2 * 128 * AS + 128) * sizeof(float);
    cudaFuncSetAttribute(mlp_kernel, cudaFuncAttributeMaxDynamicSharedMemorySize, (int)smem);
    int mlp_blocks = (natoms + 127) / 128;
    mlp_kernel<<<mlp_blocks, 512, smem>>>(W1, b1, W2, b2, W3, b3, W4, out, natoms);
}

// round 4
// speedup vs baseline: 2.2215x; 1.8111x over previous
#include <cuda_runtime.h>
#include <cuda_bf16.h>
#include <cstdint>

#define EMB 128
#define MAX_ATOMS 20000
#define AP 136                      // padded row stride (bf16 elems) = 272 B

// ---------------------------------------------------------------------------
// Device globals (no allocs allowed)
// ---------------------------------------------------------------------------
__device__ __align__(16) float g_node[MAX_ATOMS * EMB];           // segment-sum acc
__device__ __align__(16) __nv_bfloat16 g_wb[4 * 2 * 128 * AP];    // [layer][hi/lo][n*AP+k]
__device__ int g_is64;

// ---------------------------------------------------------------------------
__device__ __forceinline__ uint32_t smem_to_u32(const void* p) {
    uint32_t a;
    asm("{ .reg .u64 t; cvta.to.shared.u64 t, %1; cvt.u32.u64 %0, t; }" : "=r"(a) : "l"(p));
    return a;
}

__device__ __forceinline__ void ldsm_x4(uint32_t addr, uint32_t r[4]) {
    asm volatile("ldmatrix.sync.aligned.m8n8.x4.shared.b16 {%0,%1,%2,%3}, [%4];"
                 : "=r"(r[0]), "=r"(r[1]), "=r"(r[2]), "=r"(r[3]) : "r"(addr));
}

__device__ __forceinline__ void mma16816(float d[4], const uint32_t a[4],
                                         uint32_t b0, uint32_t b1) {
    asm volatile(
        "mma.sync.aligned.m16n8k16.row.col.f32.bf16.bf16.f32 "
        "{%0,%1,%2,%3}, {%4,%5,%6,%7}, {%8,%9}, {%0,%1,%2,%3};"
        : "+f"(d[0]), "+f"(d[1]), "+f"(d[2]), "+f"(d[3])
        : "r"(a[0]), "r"(a[1]), "r"(a[2]), "r"(a[3]), "r"(b0), "r"(b1));
}

__device__ __forceinline__ uint32_t pack_bf16x2(float x, float y) {
    __nv_bfloat162 v;
    v.x = __float2bfloat16_rn(x);
    v.y = __float2bfloat16_rn(y);
    return *reinterpret_cast<uint32_t*>(&v);
}

// ---------------------------------------------------------------------------
// Small kernels
// ---------------------------------------------------------------------------
__global__ void detect_dtype_kernel(const int* __restrict__ nbr, int n_words) {
    __shared__ int any;
    if (threadIdx.x == 0) any = 0;
    __syncthreads();
    int found = 0;
    for (int i = threadIdx.x; i < 2048; i += blockDim.x) {
        int idx = 2 * i + 1;
        if (idx < n_words && nbr[idx] != 0) found = 1;
    }
    if (found) atomicOr(&any, 1);
    __syncthreads();
    if (threadIdx.x == 0) g_is64 = (any == 0) ? 1 : 0;
}

__global__ void zero_kernel(int n4) {
    int i = blockIdx.x * blockDim.x + threadIdx.x;
    if (i < n4)
        reinterpret_cast<float4*>(g_node)[i] = make_float4(0.f, 0.f, 0.f, 0.f);
}

// Pre-split weights to bf16 hi/lo, stored transposed as B[n][k] with padded
// stride AP, ready for direct ldmatrix consumption after a verbatim smem copy.
__global__ void prep_w_kernel(const float* __restrict__ W1, const float* __restrict__ W2,
                              const float* __restrict__ W3, const float* __restrict__ W4) {
    int idx = blockIdx.x * blockDim.x + threadIdx.x;
    if (idx >= 4 * 16384) return;
    int l = idx >> 14;
    int e = idx & 16383;
    int k = e >> 7, n = e & 127;      // W row-major: W[k][n]
    const float* W = (l == 0) ? W1 : (l == 1) ? W2 : (l == 2) ? W3 : W4;
    float x = W[e];
    __nv_bfloat16 hi = __float2bfloat16_rn(x);
    __nv_bfloat16 lo = __float2bfloat16_rn(x - __bfloat162float(hi));
    g_wb[(l * 2 + 0) * (128 * AP) + n * AP + k] = hi;
    g_wb[(l * 2 + 1) * (128 * AP) + n * AP + k] = lo;
}

// ---------------------------------------------------------------------------
// Edge pass: one warp handles 4 edges; front-batched loads.
// ---------------------------------------------------------------------------
__global__ void __launch_bounds__(256) edge_kernel(
    const float* __restrict__ m_ji,
    const float* __restrict__ e_rbf,
    const int*   __restrict__ nbr,
    const float* __restrict__ W_edge,
    int E)
{
    __shared__ float sWe[6 * 128];
    int tid = threadIdx.x;
    for (int i = tid; i < 6 * 128; i += blockDim.x) sWe[i] = W_edge[i];
    __syncthreads();

    int warp = (int)((blockIdx.x * (long long)blockDim.x + tid) >> 5);
    int lane = tid & 31;
    long long e0 = (long long)warp * 4;
    if (e0 >= E) return;
    int n = (int)min((long long)4, E - e0);
    int is64 = g_is64;

    float rbf = (lane < 6 * n) ? __ldg(&e_rbf[e0 * 6 + lane]) : 0.0f;
    int d = 0;
    if (lane < n)
        d = is64 ? __ldg(&nbr[(e0 + lane) * 4 + 2]) : __ldg(&nbr[(e0 + lane) * 2 + 1]);
    float4 m[4];
#pragma unroll
    for (int j = 0; j < 4; j++) {
        if (j < n)
            m[j] = __ldg(&reinterpret_cast<const float4*>(m_ji + (e0 + j) * EMB)[lane]);
    }

    const float4* we4 = reinterpret_cast<const float4*>(sWe);
    float4 wv[6];
#pragma unroll
    for (int r = 0; r < 6; r++) wv[r] = we4[r * 32 + lane];

#pragma unroll
    for (int j = 0; j < 4; j++) {
        if (j >= n) break;
        float4 w = make_float4(0.f, 0.f, 0.f, 0.f);
#pragma unroll
        for (int r = 0; r < 6; r++) {
            float c = __shfl_sync(0xffffffffu, rbf, j * 6 + r);
            w.x = fmaf(c, wv[r].x, w.x);
            w.y = fmaf(c, wv[r].y, w.y);
            w.z = fmaf(c, wv[r].z, w.z);
            w.w = fmaf(c, wv[r].w, w.w);
        }
        float4 o = make_float4(w.x * m[j].x, w.y * m[j].y, w.z * m[j].z, w.w * m[j].w);
        int dj = __shfl_sync(0xffffffffu, d, j);
        atomicAdd(reinterpret_cast<float4*>(&g_node[(long long)dj * EMB + lane * 4]), o);
    }
}

// ---------------------------------------------------------------------------
// MLP via mma.sync.m16n8k16 bf16 split (HMMA). 128 rows/CTA, 256 threads.
// Warp w: rows [ (w>>1)*32, +32 ), cols [ (w&1)*64, +64 ).
// smem: Ahi Alo Bhi Blo (each 128*AP bf16 = 34816 B) + bias (1536 B)
// ---------------------------------------------------------------------------
#define SA_HI 0
#define SA_LO 34816
#define SB_HI 69632
#define SB_LO 104448
#define SBIAS 139264
#define SMEM_TOTAL (139264 + 1536)

__global__ void __launch_bounds__(256, 1) mlp_kernel(
    const float* __restrict__ b1, const float* __restrict__ b2,
    const float* __restrict__ b3,
    float* __restrict__ out, int natoms)
{
    extern __shared__ char smem[];
    uint32_t sb = smem_to_u32(smem);
    int tid = threadIdx.x;
    int wid = tid >> 5;
    int lane = tid & 31;
    int wrow = wid >> 1;              // 0..3 : rows [wrow*32, +32)
    int wcol = wid & 1;               // 0..1 : cols [wcol*64, +64)
    int row0 = blockIdx.x * 128;

    // biases
    if (tid < 128) {
        float* bia = reinterpret_cast<float*>(smem + SBIAS);
        bia[tid] = b1[tid];
        bia[128 + tid] = b2[tid];
        bia[256 + tid] = b3[tid];
    }

    // First-layer A: fp32 g_node -> bf16 hi/lo, padded [row][k] layout.
    for (int i = tid; i < 128 * 32; i += 256) {
        int r = i >> 5, c4 = i & 31;
        int gr = row0 + r;
        float4 v = make_float4(0.f, 0.f, 0.f, 0.f);
        if (gr < natoms)
            v = *reinterpret_cast<const float4*>(&g_node[(long long)gr * EMB + c4 * 4]);
        __nv_bfloat16 hx = __float2bfloat16_rn(v.x), hy = __float2bfloat16_rn(v.y);
        __nv_bfloat16 hz = __float2bfloat16_rn(v.z), hw = __float2bfloat16_rn(v.w);
        float lx = v.x - __bfloat162float(hx), ly = v.y - __bfloat162float(hy);
        float lz = v.z - __bfloat162float(hz), lw = v.w - __bfloat162float(hw);
        uint2 hp, lp;
        __nv_bfloat162 t;
        t.x = hx; t.y = hy; hp.x = *reinterpret_cast<uint32_t*>(&t);
        t.x = hz; t.y = hw; hp.y = *reinterpret_cast<uint32_t*>(&t);
        lp.x = pack_bf16x2(lx, ly);
        lp.y = pack_bf16x2(lz, lw);
        *reinterpret_cast<uint2*>(smem + SA_HI + r * (AP * 2) + c4 * 8) = hp;
        *reinterpret_cast<uint2*>(smem + SA_LO + r * (AP * 2) + c4 * 8) = lp;
    }

    // ldmatrix source addresses
    // A fragment (m16k16): lane -> row (lane&15), col half (lane>>4)*8
    uint32_t a_off = (uint32_t)((wrow * 32 + (lane & 15)) * (AP * 2) + ((lane >> 4) * 8) * 2);
    uint32_t aH = sb + SA_HI + a_off;
    uint32_t aL = sb + SA_LO + a_off;
    // B fragment pair (two n-tiles x k16): group = lane>>3
    //   n_add = (group>=2)*8, k_add = (group&1)*8, row in group = lane&7
    uint32_t b_row = (uint32_t)(((lane >> 4) & 1) * 8 + (lane & 7));
    uint32_t b_k   = (uint32_t)(((lane >> 3) & 1) * 8);
    uint32_t b_off = (uint32_t)((wcol * 64 + b_row) * (AP * 2) + b_k * 2);
    uint32_t bH = sb + SB_HI + b_off;
    uint32_t bL = sb + SB_LO + b_off;

    const float* bias_all = reinterpret_cast<const float*>(smem + SBIAS);
    int g = lane >> 2;                // epilogue group row
    int t2 = (lane & 3) * 2;          // epilogue col pair

    for (int layer = 0; layer < 4; layer++) {
        __syncthreads();   // A writes (init or epilogue) visible; B safe to overwrite

        // copy this layer's pre-split weights (verbatim, already padded+transposed)
        {
            const float4* srcH = reinterpret_cast<const float4*>(g_wb + (layer * 2 + 0) * (128 * AP));
            const float4* srcL = reinterpret_cast<const float4*>(g_wb + (layer * 2 + 1) * (128 * AP));
            float4* dstH = reinterpret_cast<float4*>(smem + SB_HI);
            float4* dstL = reinterpret_cast<float4*>(smem + SB_LO);
            for (int i = tid; i < (128 * AP * 2) / 16; i += 256) {
                dstH[i] = srcH[i];
                dstL[i] = srcL[i];
            }
        }
        __syncthreads();

        float acc[2][8][4];
#pragma unroll
        for (int mt = 0; mt < 2; mt++)
#pragma unroll
            for (int nt = 0; nt < 8; nt++)
#pragma unroll
                for (int q = 0; q < 4; q++) acc[mt][nt][q] = 0.0f;

#pragma unroll
        for (int k0 = 0; k0 < 128; k0 += 16) {
            uint32_t ah[2][4], al[2][4];
#pragma unroll
            for (int mt = 0; mt < 2; mt++) {
                ldsm_x4(aH + mt * 16 * (AP * 2) + k0 * 2, ah[mt]);
                ldsm_x4(aL + mt * 16 * (AP * 2) + k0 * 2, al[mt]);
            }
#pragma unroll
            for (int nt2 = 0; nt2 < 4; nt2++) {
                uint32_t bh[4], bl[4];
                ldsm_x4(bH + nt2 * 16 * (AP * 2) + k0 * 2, bh);
                ldsm_x4(bL + nt2 * 16 * (AP * 2) + k0 * 2, bl);
#pragma unroll
                for (int nt = 0; nt < 2; nt++) {
                    int nti = nt2 * 2 + nt;
#pragma unroll
                    for (int mt = 0; mt < 2; mt++) {
                        mma16816(acc[mt][nti], ah[mt], bh[nt * 2], bh[nt * 2 + 1]);
                        mma16816(acc[mt][nti], ah[mt], bl[nt * 2], bl[nt * 2 + 1]);
                        mma16816(acc[mt][nti], al[mt], bh[nt * 2], bh[nt * 2 + 1]);
                    }
                }
            }
        }
        __syncthreads();   // all ldmatrix reads of A done before epilogue rewrites A

        if (layer < 3) {
            const float* bia = bias_all + layer * 128;
#pragma unroll
            for (int mt = 0; mt < 2; mt++) {
                int rA = wrow * 32 + mt * 16 + g;
                int rB = rA + 8;
#pragma unroll
                for (int nt = 0; nt < 8; nt++) {
                    int col = wcol * 64 + nt * 8 + t2;
                    float b0 = bia[col], b1v = bia[col + 1];
                    float x0 = acc[mt][nt][0] + b0;
                    float x1 = acc[mt][nt][1] + b1v;
                    float x2 = acc[mt][nt][2] + b0;
                    float x3 = acc[mt][nt][3] + b1v;
                    float s0 = x0 / (1.0f + __expf(-x0));
                    float s1 = x1 / (1.0f + __expf(-x1));
                    float s2 = x2 / (1.0f + __expf(-x2));
                    float s3 = x3 / (1.0f + __expf(-x3));
                    __nv_bfloat16 h0 = __float2bfloat16_rn(s0);
                    __nv_bfloat16 h1 = __float2bfloat16_rn(s1);
                    __nv_bfloat16 h2 = __float2bfloat16_rn(s2);
                    __nv_bfloat16 h3 = __float2bfloat16_rn(s3);
                    __nv_bfloat162 hv;
                    hv.x = h0; hv.y = h1;
                    *reinterpret_cast<uint32_t*>(smem + SA_HI + rA * (AP * 2) + col * 2) =
                        *reinterpret_cast<uint32_t*>(&hv);
                    hv.x = h2; hv.y = h3;
                    *reinterpret_cast<uint32_t*>(smem + SA_HI + rB * (AP * 2) + col * 2) =
                        *reinterpret_cast<uint32_t*>(&hv);
                    *reinterpret_cast<uint32_t*>(smem + SA_LO + rA * (AP * 2) + col * 2) =
                        pack_bf16x2(s0 - __bfloat162float(h0), s1 - __bfloat162float(h1));
                    *reinterpret_cast<uint32_t*>(smem + SA_LO + rB * (AP * 2) + col * 2) =
                        pack_bf16x2(s2 - __bfloat162float(h2), s3 - __bfloat162float(h3));
                }
            }
        } else {
#pragma unroll
            for (int mt = 0; mt < 2; mt++) {
                int rA = row0 + wrow * 32 + mt * 16 + g;
                int rB = rA + 8;
#pragma unroll
                for (int nt = 0; nt < 8; nt++) {
                    int col = wcol * 64 + nt * 8 + t2;
                    if (rA < natoms)
                        *reinterpret_cast<float2*>(&out[(long long)rA * EMB + col]) =
                            make_float2(acc[mt][nt][0], acc[mt][nt][1]);
                    if (rB < natoms)
                        *reinterpret_cast<float2*>(&out[(long long)rB * EMB + col]) =
                            make_float2(acc[mt][nt][2], acc[mt][nt][3]);
                }
            }
        }
    }
}

// ---------------------------------------------------------------------------
extern "C" void kernel_launch(void* const* d_in, const int* in_sizes, int n_in,
                              void* d_out, int out_size)
{
    const float* m_ji  = (const float*)d_in[0];
    const float* e_rbf = (const float*)d_in[1];
    const int*   nbr   = (const int*)d_in[2];

    int base = (n_in >= 12 && in_sizes[3] < 16) ? 4 : 3;
    const float* W_edge = (const float*)d_in[base + 0];
    const float* W1 = (const float*)d_in[base + 1];
    const float* b1 = (const float*)d_in[base + 2];
    const float* W2 = (const float*)d_in[base + 3];
    const float* b2 = (const float*)d_in[base + 4];
    const float* W3 = (const float*)d_in[base + 5];
    const float* b3 = (const float*)d_in[base + 6];
    const float* W4 = (const float*)d_in[base + 7];

    int E = in_sizes[1] / 6;
    int natoms = out_size / EMB;
    if (natoms > MAX_ATOMS) natoms = MAX_ATOMS;
    float* out = (float*)d_out;

    detect_dtype_kernel<<<1, 256>>>(nbr, 2 * E);

    int n4 = natoms * EMB / 4;
    zero_kernel<<<(n4 + 255) / 256, 256>>>(n4);

    prep_w_kernel<<<(4 * 16384 + 255) / 256, 256>>>(W1, W2, W3, W4);

    int warps = (E + 3) / 4;
    int eblocks = (warps + 7) / 8;
    edge_kernel<<<eblocks, 256>>>(m_ji, e_rbf, nbr, W_edge, E);

    cudaFuncSetAttribute(mlp_kernel, cudaFuncAttributeMaxDynamicSharedMemorySize, SMEM_TOTAL);
    int mlp_blocks = (natoms + 127) / 128;
    mlp_kernel<<<mlp_blocks, 256, SMEM_TOTAL>>>(b1, b2, b3, out, natoms);
}

// round 5
// speedup vs baseline: 2.8568x; 1.2860x over previous
#include <cuda_runtime.h>
#include <cuda_bf16.h>
#include <cstdint>

#define EMB 128
#define MAX_ATOMS 20000
#define AP 136                      // padded row stride (bf16 elems) = 272 B
#define MROWS 160                   // rows per MLP CTA (10 m16 tiles)

// ---------------------------------------------------------------------------
__device__ __align__(16) float g_node[MAX_ATOMS * EMB];           // segment-sum acc
__device__ __align__(16) __nv_bfloat16 g_wb[4 * 2 * 128 * AP];    // [layer][hi/lo][n*AP+k]
__device__ int g_is64;

// ---------------------------------------------------------------------------
__device__ __forceinline__ uint32_t smem_to_u32(const void* p) {
    uint32_t a;
    asm("{ .reg .u64 t; cvta.to.shared.u64 t, %1; cvt.u32.u64 %0, t; }" : "=r"(a) : "l"(p));
    return a;
}

__device__ __forceinline__ void ldsm_x4(uint32_t addr, uint32_t r[4]) {
    asm volatile("ldmatrix.sync.aligned.m8n8.x4.shared.b16 {%0,%1,%2,%3}, [%4];"
                 : "=r"(r[0]), "=r"(r[1]), "=r"(r[2]), "=r"(r[3]) : "r"(addr));
}

__device__ __forceinline__ void mma16816(float d[4], const uint32_t a[4],
                                         uint32_t b0, uint32_t b1) {
    asm volatile(
        "mma.sync.aligned.m16n8k16.row.col.f32.bf16.bf16.f32 "
        "{%0,%1,%2,%3}, {%4,%5,%6,%7}, {%8,%9}, {%0,%1,%2,%3};"
        : "+f"(d[0]), "+f"(d[1]), "+f"(d[2]), "+f"(d[3])
        : "r"(a[0]), "r"(a[1]), "r"(a[2]), "r"(a[3]), "r"(b0), "r"(b1));
}

__device__ __forceinline__ uint32_t pack_bf16x2(float x, float y) {
    __nv_bfloat162 v;
    v.x = __float2bfloat16_rn(x);
    v.y = __float2bfloat16_rn(y);
    return *reinterpret_cast<uint32_t*>(&v);
}

// ---------------------------------------------------------------------------
// Fused setup: zero g_node, prep weights, detect nbr dtype. One launch.
//   blocks [0, ZB)            : zero g_node (float4)
//   blocks [ZB, ZB+PB)        : weight split/transpose
//   block  ZB+PB              : dtype detect
// ---------------------------------------------------------------------------
__global__ void setup_kernel(const float* __restrict__ W1, const float* __restrict__ W2,
                             const float* __restrict__ W3, const float* __restrict__ W4,
                             const int* __restrict__ nbr, int n_words,
                             int n4, int zb)
{
    int b = blockIdx.x;
    if (b < zb) {
        int i = b * 256 + threadIdx.x;
        if (i < n4)
            reinterpret_cast<float4*>(g_node)[i] = make_float4(0.f, 0.f, 0.f, 0.f);
        return;
    }
    b -= zb;
    if (b < 256) {
        int idx = b * 256 + threadIdx.x;   // 65536 elements
        int l = idx >> 14;
        int e = idx & 16383;
        int k = e >> 7, n = e & 127;       // W row-major: W[k][n]
        const float* W = (l == 0) ? W1 : (l == 1) ? W2 : (l == 2) ? W3 : W4;
        float x = W[e];
        __nv_bfloat16 hi = __float2bfloat16_rn(x);
        __nv_bfloat16 lo = __float2bfloat16_rn(x - __bfloat162float(hi));
        g_wb[(l * 2 + 0) * (128 * AP) + n * AP + k] = hi;
        g_wb[(l * 2 + 1) * (128 * AP) + n * AP + k] = lo;
        return;
    }
    // dtype detection
    __shared__ int any;
    if (threadIdx.x == 0) any = 0;
    __syncthreads();
    int found = 0;
    for (int i = threadIdx.x; i < 2048; i += blockDim.x) {
        int idx = 2 * i + 1;
        if (idx < n_words && nbr[idx] != 0) found = 1;
    }
    if (found) atomicOr(&any, 1);
    __syncthreads();
    if (threadIdx.x == 0) g_is64 = (any == 0) ? 1 : 0;
}

// ---------------------------------------------------------------------------
// Edge pass: one warp handles 4 edges; m_ji loaded per-edge (streaming),
// slim registers for 5 CTAs/SM.
// ---------------------------------------------------------------------------
__global__ void __launch_bounds__(256, 5) edge_kernel(
    const float* __restrict__ m_ji,
    const float* __restrict__ e_rbf,
    const int*   __restrict__ nbr,
    const float* __restrict__ W_edge,
    int E)
{
    __shared__ float sWe[6 * 128];
    int tid = threadIdx.x;
    for (int i = tid; i < 6 * 128; i += blockDim.x) sWe[i] = W_edge[i];
    __syncthreads();

    int warp = (int)((blockIdx.x * (long long)blockDim.x + tid) >> 5);
    int lane = tid & 31;
    long long e0 = (long long)warp * 4;
    if (e0 >= E) return;
    int is64 = g_is64;

    // front-batched rbf (24 contiguous floats) + dst indices
    float rbf = 0.0f;
    if (lane < 24 && e0 * 6 + lane < (long long)E * 6)
        rbf = __ldcs(&e_rbf[e0 * 6 + lane]);
    int d = 0;
    if (lane < 4 && e0 + lane < E)
        d = is64 ? __ldcs(&nbr[(e0 + lane) * 4 + 2]) : __ldcs(&nbr[(e0 + lane) * 2 + 1]);

    const float4* we4 = reinterpret_cast<const float4*>(sWe);
    float4 wv[6];
#pragma unroll
    for (int r = 0; r < 6; r++) wv[r] = we4[r * 32 + lane];

#pragma unroll
    for (int j = 0; j < 4; j++) {
        if (e0 + j >= E) break;
        float4 m = __ldcs(&reinterpret_cast<const float4*>(m_ji + (e0 + j) * EMB)[lane]);
        float4 w = make_float4(0.f, 0.f, 0.f, 0.f);
#pragma unroll
        for (int r = 0; r < 6; r++) {
            float c = __shfl_sync(0xffffffffu, rbf, j * 6 + r);
            w.x = fmaf(c, wv[r].x, w.x);
            w.y = fmaf(c, wv[r].y, w.y);
            w.z = fmaf(c, wv[r].z, w.z);
            w.w = fmaf(c, wv[r].w, w.w);
        }
        float4 o = make_float4(w.x * m.x, w.y * m.y, w.z * m.z, w.w * m.w);
        int dj = __shfl_sync(0xffffffffu, d, j);
        atomicAdd(reinterpret_cast<float4*>(&g_node[(long long)dj * EMB + lane * 4]), o);
    }
}

// ---------------------------------------------------------------------------
// MLP via mma.sync.m16n8k16 bf16 split. MROWS=160 rows/CTA, 256 threads,
// grid = 125 CTAs => single wave on 148 SMs.
// m16-tiles (10 total) per warp-row-group wrow: {wrow, wrow+4, +8 if wrow<2}.
// smem: Ahi(43520) Alo(43520) Bhi(34816) Blo(34816) bias(1536)
// ---------------------------------------------------------------------------
#define SA_HI 0
#define SA_LO 43520
#define SB_HI 87040
#define SB_LO 121856
#define SBIAS 156672
#define SMEM_TOTAL (156672 + 1536)

// Barrier-free per-layer compute: MT m-tiles for this warp.
template <int MT>
__device__ __forceinline__ void layer_compute(
    uint32_t aH, uint32_t aL, uint32_t bH, uint32_t bL,
    const int* tiles, float acc[][8][4])
{
#pragma unroll
    for (int mt = 0; mt < MT; mt++)
#pragma unroll
        for (int nt = 0; nt < 8; nt++)
#pragma unroll
            for (int q = 0; q < 4; q++) acc[mt][nt][q] = 0.0f;

#pragma unroll
    for (int k0 = 0; k0 < 128; k0 += 16) {
        uint32_t ah[MT][4], al[MT][4];
#pragma unroll
        for (int mt = 0; mt < MT; mt++) {
            uint32_t toff = (uint32_t)(tiles[mt] * 16 * (AP * 2)) + k0 * 2;
            ldsm_x4(aH + toff, ah[mt]);
            ldsm_x4(aL + toff, al[mt]);
        }
#pragma unroll
        for (int nt2 = 0; nt2 < 4; nt2++) {
            uint32_t bh[4], bl[4];
            ldsm_x4(bH + nt2 * 16 * (AP * 2) + k0 * 2, bh);
            ldsm_x4(bL + nt2 * 16 * (AP * 2) + k0 * 2, bl);
#pragma unroll
            for (int nt = 0; nt < 2; nt++) {
                int nti = nt2 * 2 + nt;
#pragma unroll
                for (int mt = 0; mt < MT; mt++) {
                    mma16816(acc[mt][nti], ah[mt], bh[nt * 2], bh[nt * 2 + 1]);
                    mma16816(acc[mt][nti], ah[mt], bl[nt * 2], bl[nt * 2 + 1]);
                    mma16816(acc[mt][nti], al[mt], bh[nt * 2], bh[nt * 2 + 1]);
                }
            }
        }
    }
}

template <int MT>
__device__ __forceinline__ void layer_epilogue_act(
    char* smem, const float* bia, const int* tiles, float acc[][8][4],
    int wcol, int g, int t2)
{
#pragma unroll
    for (int mt = 0; mt < MT; mt++) {
        int rA = tiles[mt] * 16 + g;
        int rB = rA + 8;
#pragma unroll
        for (int nt = 0; nt < 8; nt++) {
            int col = wcol * 64 + nt * 8 + t2;
            float b0 = bia[col], b1v = bia[col + 1];
            float x0 = acc[mt][nt][0] + b0;
            float x1 = acc[mt][nt][1] + b1v;
            float x2 = acc[mt][nt][2] + b0;
            float x3 = acc[mt][nt][3] + b1v;
            float s0 = x0 / (1.0f + __expf(-x0));
            float s1 = x1 / (1.0f + __expf(-x1));
            float s2 = x2 / (1.0f + __expf(-x2));
            float s3 = x3 / (1.0f + __expf(-x3));
            __nv_bfloat16 h0 = __float2bfloat16_rn(s0);
            __nv_bfloat16 h1 = __float2bfloat16_rn(s1);
            __nv_bfloat16 h2 = __float2bfloat16_rn(s2);
            __nv_bfloat16 h3 = __float2bfloat16_rn(s3);
            __nv_bfloat162 hv;
            hv.x = h0; hv.y = h1;
            *reinterpret_cast<uint32_t*>(smem + SA_HI + rA * (AP * 2) + col * 2) =
                *reinterpret_cast<uint32_t*>(&hv);
            hv.x = h2; hv.y = h3;
            *reinterpret_cast<uint32_t*>(smem + SA_HI + rB * (AP * 2) + col * 2) =
                *reinterpret_cast<uint32_t*>(&hv);
            *reinterpret_cast<uint32_t*>(smem + SA_LO + rA * (AP * 2) + col * 2) =
                pack_bf16x2(s0 - __bfloat162float(h0), s1 - __bfloat162float(h1));
            *reinterpret_cast<uint32_t*>(smem + SA_LO + rB * (AP * 2) + col * 2) =
                pack_bf16x2(s2 - __bfloat162float(h2), s3 - __bfloat162float(h3));
        }
    }
}

template <int MT>
__device__ __forceinline__ void layer_epilogue_out(
    float* __restrict__ out, const int* tiles, float acc[][8][4],
    int row0, int natoms, int wcol, int g, int t2)
{
#pragma unroll
    for (int mt = 0; mt < MT; mt++) {
        int rA = row0 + tiles[mt] * 16 + g;
        int rB = rA + 8;
#pragma unroll
        for (int nt = 0; nt < 8; nt++) {
            int col = wcol * 64 + nt * 8 + t2;
            if (rA < natoms)
                *reinterpret_cast<float2*>(&out[(long long)rA * EMB + col]) =
                    make_float2(acc[mt][nt][0], acc[mt][nt][1]);
            if (rB < natoms)
                *reinterpret_cast<float2*>(&out[(long long)rB * EMB + col]) =
                    make_float2(acc[mt][nt][2], acc[mt][nt][3]);
        }
    }
}

__global__ void __launch_bounds__(256, 1) mlp_kernel(
    const float* __restrict__ b1, const float* __restrict__ b2,
    const float* __restrict__ b3,
    float* __restrict__ out, int natoms)
{
    extern __shared__ char smem[];
    uint32_t sb = smem_to_u32(smem);
    int tid = threadIdx.x;
    int wid = tid >> 5;
    int lane = tid & 31;
    int wrow = wid >> 1;              // 0..3
    int wcol = wid & 1;               // 0..1
    int row0 = blockIdx.x * MROWS;

    // m16-tile assignment: {wrow, wrow+4} plus wrow+8 when wrow<2
    int tiles[3];
    tiles[0] = wrow;
    tiles[1] = wrow + 4;
    tiles[2] = wrow + 8;              // valid only for wrow<2
    bool has3 = (wrow < 2);

    if (tid < 128) {
        float* bia = reinterpret_cast<float*>(smem + SBIAS);
        bia[tid] = b1[tid];
        bia[128 + tid] = b2[tid];
        bia[256 + tid] = b3[tid];
    }

    // First-layer A: fp32 g_node -> bf16 hi/lo, padded [row][k] layout.
    for (int i = tid; i < MROWS * 32; i += 256) {
        int r = i >> 5, c4 = i & 31;
        int gr = row0 + r;
        float4 v = make_float4(0.f, 0.f, 0.f, 0.f);
        if (gr < natoms)
            v = __ldcs(&reinterpret_cast<const float4*>(&g_node[(long long)gr * EMB])[c4]);
        __nv_bfloat16 hx = __float2bfloat16_rn(v.x), hy = __float2bfloat16_rn(v.y);
        __nv_bfloat16 hz = __float2bfloat16_rn(v.z), hw = __float2bfloat16_rn(v.w);
        uint2 hp, lp;
        __nv_bfloat162 t;
        t.x = hx; t.y = hy; hp.x = *reinterpret_cast<uint32_t*>(&t);
        t.x = hz; t.y = hw; hp.y = *reinterpret_cast<uint32_t*>(&t);
        lp.x = pack_bf16x2(v.x - __bfloat162float(hx), v.y - __bfloat162float(hy));
        lp.y = pack_bf16x2(v.z - __bfloat162float(hz), v.w - __bfloat162float(hw));
        *reinterpret_cast<uint2*>(smem + SA_HI + r * (AP * 2) + c4 * 8) = hp;
        *reinterpret_cast<uint2*>(smem + SA_LO + r * (AP * 2) + c4 * 8) = lp;
    }

    // ldmatrix lane addressing (row tile base added per-tile)
    uint32_t a_lane = (uint32_t)((lane & 15) * (AP * 2) + ((lane >> 4) * 8) * 2);
    uint32_t aH = sb + SA_HI + a_lane;
    uint32_t aL = sb + SA_LO + a_lane;
    uint32_t b_row = (uint32_t)(((lane >> 4) & 1) * 8 + (lane & 7));
    uint32_t b_k   = (uint32_t)(((lane >> 3) & 1) * 8);
    uint32_t b_off = (uint32_t)((wcol * 64 + b_row) * (AP * 2) + b_k * 2);
    uint32_t bH = sb + SB_HI + b_off;
    uint32_t bL = sb + SB_LO + b_off;

    const float* bias_all = reinterpret_cast<const float*>(smem + SBIAS);
    int g = lane >> 2;
    int t2 = (lane & 3) * 2;

    float acc[3][8][4];

    for (int layer = 0; layer < 4; layer++) {
        __syncthreads();   // A writes visible; B safe to overwrite

        // copy this layer's pre-split weights
        {
            const float4* srcH = reinterpret_cast<const float4*>(g_wb + (layer * 2 + 0) * (128 * AP));
            const float4* srcL = reinterpret_cast<const float4*>(g_wb + (layer * 2 + 1) * (128 * AP));
            float4* dstH = reinterpret_cast<float4*>(smem + SB_HI);
            float4* dstL = reinterpret_cast<float4*>(smem + SB_LO);
            for (int i = tid; i < (128 * AP * 2) / 16; i += 256) {
                dstH[i] = srcH[i];
                dstL[i] = srcL[i];
            }
        }
        __syncthreads();

        if (has3) layer_compute<3>(aH, aL, bH, bL, tiles, acc);
        else      layer_compute<2>(aH, aL, bH, bL, tiles, acc);

        __syncthreads();   // all A reads done before epilogue rewrites A

        if (layer < 3) {
            const float* bia = bias_all + layer * 128;
            if (has3) layer_epilogue_act<3>(smem, bia, tiles, acc, wcol, g, t2);
            else      layer_epilogue_act<2>(smem, bia, tiles, acc, wcol, g, t2);
        } else {
            if (has3) layer_epilogue_out<3>(out, tiles, acc, row0, natoms, wcol, g, t2);
            else      layer_epilogue_out<2>(out, tiles, acc, row0, natoms, wcol, g, t2);
        }
    }
}

// ---------------------------------------------------------------------------
extern "C" void kernel_launch(void* const* d_in, const int* in_sizes, int n_in,
                              void* d_out, int out_size)
{
    const float* m_ji  = (const float*)d_in[0];
    const float* e_rbf = (const float*)d_in[1];
    const int*   nbr   = (const int*)d_in[2];

    int base = (n_in >= 12 && in_sizes[3] < 16) ? 4 : 3;
    const float* W_edge = (const float*)d_in[base + 0];
    const float* W1 = (const float*)d_in[base + 1];
    const float* b1 = (const float*)d_in[base + 2];
    const float* W2 = (const float*)d_in[base + 3];
    const float* b2 = (const float*)d_in[base + 4];
    const float* W3 = (const float*)d_in[base + 5];
    const float* b3 = (const float*)d_in[base + 6];
    const float* W4 = (const float*)d_in[base + 7];

    int E = in_sizes[1] / 6;
    int natoms = out_size / EMB;
    if (natoms > MAX_ATOMS) natoms = MAX_ATOMS;
    float* out = (float*)d_out;

    // fused setup: zero + weight prep + dtype detect
    int n4 = natoms * EMB / 4;
    int zb = (n4 + 255) / 256;
    setup_kernel<<<zb + 256 + 1, 256>>>(W1, W2, W3, W4, nbr, 2 * E, n4, zb);

    // edge pass
    int warps = (E + 3) / 4;
    int eblocks = (warps + 7) / 8;
    edge_kernel<<<eblocks, 256>>>(m_ji, e_rbf, nbr, W_edge, E);

    // MLP: single wave of 125 CTAs
    cudaFuncSetAttribute(mlp_kernel, cudaFuncAttributeMaxDynamicSharedMemorySize, SMEM_TOTAL);
    int mlp_blocks = (natoms + MROWS - 1) / MROWS;
    mlp_kernel<<<mlp_blocks, 256, SMEM_TOTAL>>>(b1, b2, b3, out, natoms);
}